// round 4
// baseline (speedup 1.0000x reference)
#include <cuda_runtime.h>

// Fused Canny pipeline, B=16, C=3, H=W=512 fp32.
// s = gauss_blur(sum_c img) (replicate pad); gx,gy = sobel(s)/3 (replicate pad);
// mag = sqrt(gx^2+gy^2); orientation bin via monotone thresholds on gy/gx;
// directional NMS (zero-pad outside image) -> thinned edges.
//
// Interior blocks (77%) take a fully vectorized path: float4 LDG, LDS.128
// window reads, STS.128 stores, no boundary clamps/masks. Boundary blocks use
// the scalar clamped path (replicate-pad trick: csum slots hold clamped data,
// so stage 2 clamps only its own center coord and stage 3 needs no clamps).

#define HH 512
#define WW 512
#define HW (HH * WW)
#define TS 32
#define CS 40   // csum row stride (floats)
#define BSR 40  // sblur row stride (floats)
#define MS 36   // smag / spidx row stride

__global__ __launch_bounds__(256, 5)
void canny_fused_kernel(const float* __restrict__ img,
                        const float* __restrict__ wg,
                        const float* __restrict__ wsx,
                        const float* __restrict__ wsy,
                        float* __restrict__ out)
{
    // bufA: csum[38][40] (1520 f) aliased later by smag[34][36] (1224 f) +
    // spidx 34*36 bytes (306 f). bufB: sblur[36][40].
    // Both 16B-aligned (LDS.128/STS.128); bufA padded to 1532 so any
    // follow-on allocation stays 16B-aligned too.
    __shared__ __align__(16) float bufA[1532];
    __shared__ __align__(16) float bufB[36 * BSR];

    float* csum  = bufA;
    float* sblur = bufB;
    float* smag  = bufA;
    unsigned char* spidx = reinterpret_cast<unsigned char*>(bufA + 34 * MS);

    const int b  = blockIdx.z;
    const int ox = blockIdx.x * TS;
    const int oy = blockIdx.y * TS;
    const int tid = threadIdx.x;
    const float* imgb = img + (size_t)b * 3 * HW;

    const bool interior = (ox >= TS) && (ox < WW - TS) && (oy >= TS) && (oy < HH - TS);

    const float g0 = __ldg(wg + 0), g1 = __ldg(wg + 1), g2 = __ldg(wg + 2);
    const float g3 = __ldg(wg + 3), g4 = __ldg(wg + 4), g5 = __ldg(wg + 5);
    const float g6 = __ldg(wg + 6), g7 = __ldg(wg + 7), g8 = __ldg(wg + 8);
    // sobel weights (exact structural zeros omitted: wsx col-1, wsy row-1)
    const float x0 = __ldg(wsx + 0), x2 = __ldg(wsx + 2);
    const float x3 = __ldg(wsx + 3), x5 = __ldg(wsx + 5);
    const float x6 = __ldg(wsx + 6), x8 = __ldg(wsx + 8);
    const float y0 = __ldg(wsy + 0), y1 = __ldg(wsy + 1), y2 = __ldg(wsy + 2);
    const float y6 = __ldg(wsy + 6), y7 = __ldg(wsy + 7), y8 = __ldg(wsy + 8);

    const float T0 = 0.19891237f, T1 = 0.66817864f, T2 = 1.4966058f, T3 = 5.0273395f;

    if (interior) {
        // ---- S1: channel sum, float4 in / float4 out. 38 rows x 10 quads ----
        #pragma unroll
        for (int it = 0; it < 2; it++) {
            int t = tid + it * 256;
            if (t < 380) {
                int j = t / 10, v = t - j * 10;
                const float* rowp = imgb + (size_t)(oy - 3 + j) * WW + (ox - 4);
                float4 p0 = __ldg(reinterpret_cast<const float4*>(rowp) + v);
                float4 p1 = __ldg(reinterpret_cast<const float4*>(rowp + HW) + v);
                float4 p2 = __ldg(reinterpret_cast<const float4*>(rowp + 2 * HW) + v);
                float4 s;
                s.x = p0.x + p1.x + p2.x;
                s.y = p0.y + p1.y + p2.y;
                s.z = p0.z + p1.z + p2.z;
                s.w = p0.w + p1.w + p2.w;
                *reinterpret_cast<float4*>(csum + j * CS + 4 * v) = s;
            }
        }
        __syncthreads();

        // ---- S2: blur, 4-wide per thread. 36 rows x 9 quads = 324 ----
        // output col i (x=ox-2+i) uses csum cols i+1..i+3; 4 outputs need
        // cols i+1..i+6, loaded as cols i..i+7 (two aligned float4 per row).
        #pragma unroll
        for (int it = 0; it < 2; it++) {
            int t = tid + it * 256;
            if (t < 324) {
                int j = t / 9, i = (t - j * 9) * 4;
                const float* cp = csum + j * CS + i;
                float4 a0 = *reinterpret_cast<const float4*>(cp);
                float4 a1 = *reinterpret_cast<const float4*>(cp + 4);
                float4 b0 = *reinterpret_cast<const float4*>(cp + CS);
                float4 b1 = *reinterpret_cast<const float4*>(cp + CS + 4);
                float4 c0 = *reinterpret_cast<const float4*>(cp + 2 * CS);
                float4 c1 = *reinterpret_cast<const float4*>(cp + 2 * CS + 4);
                float A[8] = {a0.x, a0.y, a0.z, a0.w, a1.x, a1.y, a1.z, a1.w};
                float B[8] = {b0.x, b0.y, b0.z, b0.w, b1.x, b1.y, b1.z, b1.w};
                float C[8] = {c0.x, c0.y, c0.z, c0.w, c1.x, c1.y, c1.z, c1.w};
                float o[4];
                #pragma unroll
                for (int e = 0; e < 4; e++)
                    o[e] = g0 * A[e + 1] + g1 * A[e + 2] + g2 * A[e + 3]
                         + g3 * B[e + 1] + g4 * B[e + 2] + g5 * B[e + 3]
                         + g6 * C[e + 1] + g7 * C[e + 2] + g8 * C[e + 3];
                *reinterpret_cast<float4*>(sblur + j * BSR + i) =
                    make_float4(o[0], o[1], o[2], o[3]);
            }
        }
        __syncthreads();

        // ---- S3: sobel + mag + bin, 4-wide. 34 rows x 9 quads = 306 ----
        // output col i uses sblur cols i..i+2; 4 outputs need cols i..i+5,
        // loaded as i..i+7. q=8 computes junk cols 34,35 (never read).
        // Interior => every output coord is in-image: no masks.
        #pragma unroll
        for (int it = 0; it < 2; it++) {
            int t = tid + it * 256;
            if (t < 306) {
                int j = t / 9, i = (t - j * 9) * 4;
                const float* sp = sblur + j * BSR + i;
                float4 a0 = *reinterpret_cast<const float4*>(sp);
                float4 a1 = *reinterpret_cast<const float4*>(sp + 4);
                float4 b0 = *reinterpret_cast<const float4*>(sp + BSR);
                float4 b1 = *reinterpret_cast<const float4*>(sp + BSR + 4);
                float4 c0 = *reinterpret_cast<const float4*>(sp + 2 * BSR);
                float4 c1 = *reinterpret_cast<const float4*>(sp + 2 * BSR + 4);
                float A[8] = {a0.x, a0.y, a0.z, a0.w, a1.x, a1.y, a1.z, a1.w};
                float B[8] = {b0.x, b0.y, b0.z, b0.w, b1.x, b1.y, b1.z, b1.w};
                float C[8] = {c0.x, c0.y, c0.z, c0.w, c1.x, c1.y, c1.z, c1.w};
                float mg[4];
                unsigned pack = 0;
                #pragma unroll
                for (int e = 0; e < 4; e++) {
                    float gx = x0 * A[e] + x2 * A[e + 2] + x3 * B[e] + x5 * B[e + 2]
                             + x6 * C[e] + x8 * C[e + 2];
                    float gy = y0 * A[e] + y1 * A[e + 1] + y2 * A[e + 2]
                             + y6 * C[e] + y7 * C[e + 1] + y8 * C[e + 2];
                    mg[e] = sqrtf(gx * gx + gy * gy) * 0.3333333433f;
                    float r  = __fdividef(gy, gx);
                    float ta = fabsf(r);
                    int m = (ta > T0) + (ta > T1) + (ta > T2) + (ta > T3);
                    int qm = (r > 0.0f) ? (m & 3) : ((4 - m) & 3);
                    pack |= (unsigned)qm << (8 * e);
                }
                *reinterpret_cast<float4*>(smag + j * MS + i) =
                    make_float4(mg[0], mg[1], mg[2], mg[3]);
                *reinterpret_cast<unsigned*>(spidx + j * MS + i) = pack;
            }
        }
    } else {
        // ---- boundary path: scalar with clamped coordinates ----
        #pragma unroll
        for (int it = 0; it < 6; it++) {
            int t = tid + it * 256;
            if (t < 1520) {                      // 38 x 40
                int j = t / 40, i = t - j * 40;
                int y = min(max(oy - 3 + j, 0), HH - 1);
                int x = min(max(ox - 4 + i, 0), WW - 1);
                int o = y * WW + x;
                csum[j * CS + i] = __ldg(imgb + o)
                                 + __ldg(imgb + HW + o)
                                 + __ldg(imgb + 2 * HW + o);
            }
        }
        __syncthreads();
        // clamp center coord once; neighbors land on already-clamped csum
        // slots, giving exact replicate-pad blur.
        #pragma unroll
        for (int it = 0; it < 6; it++) {
            int t = tid + it * 256;
            if (t < 1296) {                      // 36 x 36
                int j = t / 36, i = t - j * 36;
                int yc = min(max(oy - 2 + j, 0), HH - 1);
                int xc = min(max(ox - 2 + i, 0), WW - 1);
                int r1 = yc - (oy - 3);
                int c1 = xc - (ox - 4);
                const float* cp = csum + (r1 - 1) * CS + (c1 - 1);
                sblur[j * BSR + i] =
                      g0 * cp[0]      + g1 * cp[1]      + g2 * cp[2]
                    + g3 * cp[CS]     + g4 * cp[CS + 1] + g5 * cp[CS + 2]
                    + g6 * cp[2 * CS] + g7 * cp[2*CS+1] + g8 * cp[2*CS+2];
            }
        }
        __syncthreads();
        // sobel + mag + bin, 2-wide scalar, with in-image masking (mag=0
        // outside => zero-pad semantics for the directional conv).
        #pragma unroll
        for (int it = 0; it < 3; it++) {
            int t = tid + it * 256;
            if (t < 578) {                       // 34 rows x 17 pairs
                int j = t / 17;
                int i = (t - j * 17) * 2;
                const float* sp = sblur + j * BSR + i;
                float s00 = sp[0],        s01 = sp[1],        s02 = sp[2],        s03 = sp[3];
                float s10 = sp[BSR],      s11 = sp[BSR + 1],  s12 = sp[BSR + 2],  s13 = sp[BSR + 3];
                float s20 = sp[2 * BSR],  s21 = sp[2*BSR+1],  s22 = sp[2*BSR+2],  s23 = sp[2*BSR+3];
                int yq = oy - 1 + j;
                int xq = ox - 1 + i;
                bool iny = ((unsigned)yq < (unsigned)HH);
                {
                    float gx = x0*s00 + x2*s02 + x3*s10 + x5*s12 + x6*s20 + x8*s22;
                    float gy = y0*s00 + y1*s01 + y2*s02 + y6*s20 + y7*s21 + y8*s22;
                    float mg = sqrtf(gx * gx + gy * gy) * 0.3333333433f;
                    float r  = __fdividef(gy, gx);
                    float ta = fabsf(r);
                    int m = (ta > T0) + (ta > T1) + (ta > T2) + (ta > T3);
                    int qm = (r > 0.0f) ? (m & 3) : ((4 - m) & 3);
                    bool in0 = iny && ((unsigned)xq < (unsigned)WW);
                    smag[j * MS + i]  = in0 ? mg : 0.0f;
                    spidx[j * MS + i] = (unsigned char)qm;
                }
                {
                    float gx = x0*s01 + x2*s03 + x3*s11 + x5*s13 + x6*s21 + x8*s23;
                    float gy = y0*s01 + y1*s02 + y2*s03 + y6*s21 + y7*s22 + y8*s23;
                    float mg = sqrtf(gx * gx + gy * gy) * 0.3333333433f;
                    float r  = __fdividef(gy, gx);
                    float ta = fabsf(r);
                    int m = (ta > T0) + (ta > T1) + (ta > T2) + (ta > T3);
                    int qm = (r > 0.0f) ? (m & 3) : ((4 - m) & 3);
                    bool in1 = iny && ((unsigned)(xq + 1) < (unsigned)WW);
                    smag[j * MS + i + 1]  = in1 ? mg : 0.0f;
                    spidx[j * MS + i + 1] = (unsigned char)qm;
                }
            }
        }
    }
    __syncthreads();

    // ---- S4: directional NMS + write ----
    // bin&3 -> neighbor offset (dy,dx): 0:(0,1) 1:(-1,1) 2:(-1,0) 3:(-1,-1)
    const size_t base = ((size_t)b * HH + oy) * WW + ox;
    #pragma unroll
    for (int it = 0; it < 4; it++) {
        int idx = tid + it * 256;
        int j = idx >> 5, i = idx & 31;
        const float* mrow = smag + (j + 1) * MS + (i + 1);
        float m = mrow[0];
        int q = spidx[(j + 1) * MS + (i + 1)] & 3;
        int dy = (q == 0) ? 0 : -1;
        int dx = (q == 3) ? -1 : ((q == 2) ? 0 : 1);
        int off = dy * MS + dx;
        float n1 = mrow[off];
        float n2 = mrow[-off];
        out[base + (size_t)j * WW + i] = (m - n1 > 0.0f && m - n2 > 0.0f) ? m : 0.0f;
    }
}

extern "C" void kernel_launch(void* const* d_in, const int* in_sizes, int n_in,
                              void* d_out, int out_size)
{
    const float* img = (const float*)d_in[0];
    const float* wg  = (const float*)d_in[1];
    const float* wsx = (const float*)d_in[2];
    const float* wsy = (const float*)d_in[3];
    // d_in[4] = w_dir: structurally fixed (+1 center, -1 rotated neighbor);
    // offsets hardcoded in stage 4.
    float* out = (float*)d_out;

    dim3 grid(WW / TS, HH / TS, 16);
    canny_fused_kernel<<<grid, 256>>>(img, wg, wsx, wsy, out);
}

// round 5
// speedup vs baseline: 1.0738x; 1.0738x over previous
#include <cuda_runtime.h>

// Fused Canny pipeline, B=16, C=3, H=W=512 fp32.
// s = gauss_blur(sum_c img) (replicate pad); gx,gy = sobel(s)/3 (replicate pad);
// mag = sqrt(gx^2+gy^2); orientation bin via monotone thresholds on gy/gx;
// directional NMS (zero-pad outside image) -> thinned edges.
//
// Interior blocks: vectorized path with 4-wide x 2-row strips per thread in
// the stencil stages -- 4 input rows serve 2 output rows through registers,
// cutting smem read bytes 33% (L1 crossbar is the measured bottleneck).
// Boundary blocks: scalar clamped path (replicate-pad trick: csum slots hold
// clamped data, stage 2 clamps only its own center coord, stage 3 clamp-free).

#define HH 512
#define WW 512
#define HW (HH * WW)
#define TS 32
#define CS 40   // csum row stride (floats)
#define BSR 40  // sblur row stride (floats)
#define MS 36   // smag / spidx row stride

__global__ __launch_bounds__(256, 4)
void canny_fused_kernel(const float* __restrict__ img,
                        const float* __restrict__ wg,
                        const float* __restrict__ wsx,
                        const float* __restrict__ wsy,
                        float* __restrict__ out)
{
    // bufA: csum[38][40] (1520 f) aliased later by smag[34][36] (1224 f) +
    // spidx 34*36 bytes (306 f). bufB: sblur[36][40]. Both 16B-aligned.
    __shared__ __align__(16) float bufA[1532];
    __shared__ __align__(16) float bufB[36 * BSR];

    float* csum  = bufA;
    float* sblur = bufB;
    float* smag  = bufA;
    unsigned char* spidx = reinterpret_cast<unsigned char*>(bufA + 34 * MS);

    const int b  = blockIdx.z;
    const int ox = blockIdx.x * TS;
    const int oy = blockIdx.y * TS;
    const int tid = threadIdx.x;
    const float* imgb = img + (size_t)b * 3 * HW;

    const bool interior = (ox >= TS) && (ox < WW - TS) && (oy >= TS) && (oy < HH - TS);

    const float g0 = __ldg(wg + 0), g1 = __ldg(wg + 1), g2 = __ldg(wg + 2);
    const float g3 = __ldg(wg + 3), g4 = __ldg(wg + 4), g5 = __ldg(wg + 5);
    const float g6 = __ldg(wg + 6), g7 = __ldg(wg + 7), g8 = __ldg(wg + 8);
    // sobel weights (exact structural zeros omitted: wsx col-1, wsy row-1)
    const float x0 = __ldg(wsx + 0), x2 = __ldg(wsx + 2);
    const float x3 = __ldg(wsx + 3), x5 = __ldg(wsx + 5);
    const float x6 = __ldg(wsx + 6), x8 = __ldg(wsx + 8);
    const float y0 = __ldg(wsy + 0), y1 = __ldg(wsy + 1), y2 = __ldg(wsy + 2);
    const float y6 = __ldg(wsy + 6), y7 = __ldg(wsy + 7), y8 = __ldg(wsy + 8);

    const float T0 = 0.19891237f, T1 = 0.66817864f, T2 = 1.4966058f, T3 = 5.0273395f;

    if (interior) {
        // ---- S1: channel sum, float4 in / float4 out. 38 rows x 10 quads ----
        #pragma unroll
        for (int it = 0; it < 2; it++) {
            int t = tid + it * 256;
            if (t < 380) {
                int j = t / 10, v = t - j * 10;
                const float* rowp = imgb + (size_t)(oy - 3 + j) * WW + (ox - 4);
                float4 p0 = __ldg(reinterpret_cast<const float4*>(rowp) + v);
                float4 p1 = __ldg(reinterpret_cast<const float4*>(rowp + HW) + v);
                float4 p2 = __ldg(reinterpret_cast<const float4*>(rowp + 2 * HW) + v);
                float4 s;
                s.x = p0.x + p1.x + p2.x;
                s.y = p0.y + p1.y + p2.y;
                s.z = p0.z + p1.z + p2.z;
                s.w = p0.w + p1.w + p2.w;
                *reinterpret_cast<float4*>(csum + j * CS + 4 * v) = s;
            }
        }
        __syncthreads();

        // ---- S2: blur, 4-wide x 2-row strip. 18 pairs x 9 quads = 162 ----
        // sblur row s (y=oy-2+s) needs csum rows s..s+2; pair (s,s+1) shares
        // csum rows s..s+3: 8 LDS.128 serve 8 outputs (16B/output).
        if (tid < 162) {
            int p = tid / 9, q = tid - p * 9;
            int s = 2 * p, i = 4 * q;
            const float* cp = csum + s * CS + i;
            float4 r0a = *reinterpret_cast<const float4*>(cp);
            float4 r0b = *reinterpret_cast<const float4*>(cp + 4);
            float4 r1a = *reinterpret_cast<const float4*>(cp + CS);
            float4 r1b = *reinterpret_cast<const float4*>(cp + CS + 4);
            float4 r2a = *reinterpret_cast<const float4*>(cp + 2 * CS);
            float4 r2b = *reinterpret_cast<const float4*>(cp + 2 * CS + 4);
            float4 r3a = *reinterpret_cast<const float4*>(cp + 3 * CS);
            float4 r3b = *reinterpret_cast<const float4*>(cp + 3 * CS + 4);
            float R0[8] = {r0a.x, r0a.y, r0a.z, r0a.w, r0b.x, r0b.y, r0b.z, r0b.w};
            float R1[8] = {r1a.x, r1a.y, r1a.z, r1a.w, r1b.x, r1b.y, r1b.z, r1b.w};
            float R2[8] = {r2a.x, r2a.y, r2a.z, r2a.w, r2b.x, r2b.y, r2b.z, r2b.w};
            float R3[8] = {r3a.x, r3a.y, r3a.z, r3a.w, r3b.x, r3b.y, r3b.z, r3b.w};
            float o0[4], o1[4];
            #pragma unroll
            for (int e = 0; e < 4; e++) {
                o0[e] = g0 * R0[e + 1] + g1 * R0[e + 2] + g2 * R0[e + 3]
                      + g3 * R1[e + 1] + g4 * R1[e + 2] + g5 * R1[e + 3]
                      + g6 * R2[e + 1] + g7 * R2[e + 2] + g8 * R2[e + 3];
                o1[e] = g0 * R1[e + 1] + g1 * R1[e + 2] + g2 * R1[e + 3]
                      + g3 * R2[e + 1] + g4 * R2[e + 2] + g5 * R2[e + 3]
                      + g6 * R3[e + 1] + g7 * R3[e + 2] + g8 * R3[e + 3];
            }
            *reinterpret_cast<float4*>(sblur + s * BSR + i) =
                make_float4(o0[0], o0[1], o0[2], o0[3]);
            *reinterpret_cast<float4*>(sblur + (s + 1) * BSR + i) =
                make_float4(o1[0], o1[1], o1[2], o1[3]);
        }
        __syncthreads();

        // ---- S3: sobel+mag+bin, 4-wide x 2-row strip. 17x9 = 153 ----
        // smag row j (y=oy-1+j) needs sblur rows j..j+2; pair (j,j+1) shares
        // sblur rows j..j+3. Quad i..i+3 needs cols i..i+5, loaded i..i+7.
        // Junk cols 34,35 computed in q=8 (never read). Interior => no masks.
        if (tid < 153) {
            int p = tid / 9, q = tid - p * 9;
            int j = 2 * p, i = 4 * q;
            const float* sp = sblur + j * BSR + i;
            float4 r0a = *reinterpret_cast<const float4*>(sp);
            float4 r0b = *reinterpret_cast<const float4*>(sp + 4);
            float4 r1a = *reinterpret_cast<const float4*>(sp + BSR);
            float4 r1b = *reinterpret_cast<const float4*>(sp + BSR + 4);
            float4 r2a = *reinterpret_cast<const float4*>(sp + 2 * BSR);
            float4 r2b = *reinterpret_cast<const float4*>(sp + 2 * BSR + 4);
            float4 r3a = *reinterpret_cast<const float4*>(sp + 3 * BSR);
            float4 r3b = *reinterpret_cast<const float4*>(sp + 3 * BSR + 4);
            float R0[8] = {r0a.x, r0a.y, r0a.z, r0a.w, r0b.x, r0b.y, r0b.z, r0b.w};
            float R1[8] = {r1a.x, r1a.y, r1a.z, r1a.w, r1b.x, r1b.y, r1b.z, r1b.w};
            float R2[8] = {r2a.x, r2a.y, r2a.z, r2a.w, r2b.x, r2b.y, r2b.z, r2b.w};
            float R3[8] = {r3a.x, r3a.y, r3a.z, r3a.w, r3b.x, r3b.y, r3b.z, r3b.w};
            #pragma unroll
            for (int rr = 0; rr < 2; rr++) {
                const float* A = (rr == 0) ? R0 : R1;
                const float* B = (rr == 0) ? R1 : R2;
                const float* C = (rr == 0) ? R2 : R3;
                float mg[4];
                unsigned pack = 0;
                #pragma unroll
                for (int e = 0; e < 4; e++) {
                    float gx = x0 * A[e] + x2 * A[e + 2] + x3 * B[e] + x5 * B[e + 2]
                             + x6 * C[e] + x8 * C[e + 2];
                    float gy = y0 * A[e] + y1 * A[e + 1] + y2 * A[e + 2]
                             + y6 * C[e] + y7 * C[e + 1] + y8 * C[e + 2];
                    mg[e] = sqrtf(gx * gx + gy * gy) * 0.3333333433f;
                    float r  = __fdividef(gy, gx);
                    float ta = fabsf(r);
                    int m = (ta > T0) + (ta > T1) + (ta > T2) + (ta > T3);
                    int qm = (r > 0.0f) ? (m & 3) : ((4 - m) & 3);
                    pack |= (unsigned)qm << (8 * e);
                }
                *reinterpret_cast<float4*>(smag + (j + rr) * MS + i) =
                    make_float4(mg[0], mg[1], mg[2], mg[3]);
                *reinterpret_cast<unsigned*>(spidx + (j + rr) * MS + i) = pack;
            }
        }
    } else {
        // ---- boundary path: scalar with clamped coordinates ----
        #pragma unroll
        for (int it = 0; it < 6; it++) {
            int t = tid + it * 256;
            if (t < 1520) {                      // 38 x 40
                int j = t / 40, i = t - j * 40;
                int y = min(max(oy - 3 + j, 0), HH - 1);
                int x = min(max(ox - 4 + i, 0), WW - 1);
                int o = y * WW + x;
                csum[j * CS + i] = __ldg(imgb + o)
                                 + __ldg(imgb + HW + o)
                                 + __ldg(imgb + 2 * HW + o);
            }
        }
        __syncthreads();
        // clamp center coord once; neighbors land on already-clamped csum
        // slots, giving exact replicate-pad blur.
        #pragma unroll
        for (int it = 0; it < 6; it++) {
            int t = tid + it * 256;
            if (t < 1296) {                      // 36 x 36
                int j = t / 36, i = t - j * 36;
                int yc = min(max(oy - 2 + j, 0), HH - 1);
                int xc = min(max(ox - 2 + i, 0), WW - 1);
                int r1 = yc - (oy - 3);
                int c1 = xc - (ox - 4);
                const float* cp = csum + (r1 - 1) * CS + (c1 - 1);
                sblur[j * BSR + i] =
                      g0 * cp[0]      + g1 * cp[1]      + g2 * cp[2]
                    + g3 * cp[CS]     + g4 * cp[CS + 1] + g5 * cp[CS + 2]
                    + g6 * cp[2 * CS] + g7 * cp[2*CS+1] + g8 * cp[2*CS+2];
            }
        }
        __syncthreads();
        // sobel + mag + bin, 2-wide scalar, with in-image masking (mag=0
        // outside => zero-pad semantics for the directional conv).
        #pragma unroll
        for (int it = 0; it < 3; it++) {
            int t = tid + it * 256;
            if (t < 578) {                       // 34 rows x 17 pairs
                int j = t / 17;
                int i = (t - j * 17) * 2;
                const float* sp = sblur + j * BSR + i;
                float s00 = sp[0],        s01 = sp[1],        s02 = sp[2],        s03 = sp[3];
                float s10 = sp[BSR],      s11 = sp[BSR + 1],  s12 = sp[BSR + 2],  s13 = sp[BSR + 3];
                float s20 = sp[2 * BSR],  s21 = sp[2*BSR+1],  s22 = sp[2*BSR+2],  s23 = sp[2*BSR+3];
                int yq = oy - 1 + j;
                int xq = ox - 1 + i;
                bool iny = ((unsigned)yq < (unsigned)HH);
                {
                    float gx = x0*s00 + x2*s02 + x3*s10 + x5*s12 + x6*s20 + x8*s22;
                    float gy = y0*s00 + y1*s01 + y2*s02 + y6*s20 + y7*s21 + y8*s22;
                    float mg = sqrtf(gx * gx + gy * gy) * 0.3333333433f;
                    float r  = __fdividef(gy, gx);
                    float ta = fabsf(r);
                    int m = (ta > T0) + (ta > T1) + (ta > T2) + (ta > T3);
                    int qm = (r > 0.0f) ? (m & 3) : ((4 - m) & 3);
                    bool in0 = iny && ((unsigned)xq < (unsigned)WW);
                    smag[j * MS + i]  = in0 ? mg : 0.0f;
                    spidx[j * MS + i] = (unsigned char)qm;
                }
                {
                    float gx = x0*s01 + x2*s03 + x3*s11 + x5*s13 + x6*s21 + x8*s23;
                    float gy = y0*s01 + y1*s02 + y2*s03 + y6*s21 + y7*s22 + y8*s23;
                    float mg = sqrtf(gx * gx + gy * gy) * 0.3333333433f;
                    float r  = __fdividef(gy, gx);
                    float ta = fabsf(r);
                    int m = (ta > T0) + (ta > T1) + (ta > T2) + (ta > T3);
                    int qm = (r > 0.0f) ? (m & 3) : ((4 - m) & 3);
                    bool in1 = iny && ((unsigned)(xq + 1) < (unsigned)WW);
                    smag[j * MS + i + 1]  = in1 ? mg : 0.0f;
                    spidx[j * MS + i + 1] = (unsigned char)qm;
                }
            }
        }
    }
    __syncthreads();

    // ---- S4: directional NMS + write ----
    // bin&3 -> neighbor offset (dy,dx): 0:(0,1) 1:(-1,1) 2:(-1,0) 3:(-1,-1)
    const size_t base = ((size_t)b * HH + oy) * WW + ox;
    #pragma unroll
    for (int it = 0; it < 4; it++) {
        int idx = tid + it * 256;
        int j = idx >> 5, i = idx & 31;
        const float* mrow = smag + (j + 1) * MS + (i + 1);
        float m = mrow[0];
        int q = spidx[(j + 1) * MS + (i + 1)] & 3;
        int dy = (q == 0) ? 0 : -1;
        int dx = (q == 3) ? -1 : ((q == 2) ? 0 : 1);
        int off = dy * MS + dx;
        float n1 = mrow[off];
        float n2 = mrow[-off];
        out[base + (size_t)j * WW + i] = (m - n1 > 0.0f && m - n2 > 0.0f) ? m : 0.0f;
    }
}

extern "C" void kernel_launch(void* const* d_in, const int* in_sizes, int n_in,
                              void* d_out, int out_size)
{
    const float* img = (const float*)d_in[0];
    const float* wg  = (const float*)d_in[1];
    const float* wsx = (const float*)d_in[2];
    const float* wsy = (const float*)d_in[3];
    // d_in[4] = w_dir: structurally fixed (+1 center, -1 rotated neighbor);
    // offsets hardcoded in stage 4.
    float* out = (float*)d_out;

    dim3 grid(WW / TS, HH / TS, 16);
    canny_fused_kernel<<<grid, 256>>>(img, wg, wsx, wsy, out);
}